// round 2
// baseline (speedup 1.0000x reference)
#include <cuda_runtime.h>
#include <math.h>

#define NB   16
#define NP   4096
#define NS   1024
#define NK   16
#define FIN  256
#define FOUT 512
#define NTOT (NB*NP)   // 65536
#define NQ   (NB*NS)   // 16384

// ---------------- device scratch (allocation-free) ----------------
__device__ float g_h[NTOT*FOUT];        // 134 MB pre-norm MLP output
__device__ float g_xnorm[NTOT];         // ||x||^2 per point (feature space)
__device__ int   g_fps[NQ];             // global fps indices
__device__ int   g_knn[NQ*NK];          // global knn indices
__device__ float g_psum[256*FOUT];      // partial column sums
__device__ float g_psq [256*FOUT];      // partial column sumsq
__device__ float g_mu  [FOUT];
__device__ float g_rsig[FOUT];

__device__ __forceinline__ float finf() { return __int_as_float(0x7f800000); }

// ---------------- 1) farthest point sampling ----------------
// one block per cloud; 1024 threads, 4 points each; positions in smem
__global__ void k_fps(const float* __restrict__ pos) {
    extern __shared__ float sp[];          // px[4096] py[4096] pz[4096] = 48KB
    float* px = sp; float* py = sp + NP; float* pz = sp + 2*NP;
    __shared__ float rv[32];
    __shared__ int   ri[32];
    __shared__ int   s_last;

    const int b   = blockIdx.x;
    const int tid = threadIdx.x;
    const int lane = tid & 31, warp = tid >> 5;
    const float* pb = pos + (size_t)b * NP * 3;

    for (int i = tid; i < NP*3; i += 1024) {
        float v = pb[i];
        int p = i / 3, d = i - p*3;
        if (d == 0) px[p] = v; else if (d == 1) py[p] = v; else pz[p] = v;
    }
    __syncthreads();

    float md[4] = {finf(), finf(), finf(), finf()};
    int last = 0;

    for (int s = 0; s < NS; s++) {
        if (tid == 0) g_fps[b*NS + s] = b*NP + last;
        float qx = px[last], qy = py[last], qz = pz[last];

        float best = -finf(); int bi = 0;
        #pragma unroll
        for (int j = 0; j < 4; j++) {
            int p = tid + j*1024;
            float dx = px[p]-qx, dy = py[p]-qy, dz = pz[p]-qz;
            float d = dx*dx + dy*dy + dz*dz;
            float m = fminf(md[j], d);
            md[j] = m;
            if (m > best) { best = m; bi = p; }   // strict > keeps smallest p
        }
        #pragma unroll
        for (int off = 16; off; off >>= 1) {
            float ov = __shfl_down_sync(0xffffffffu, best, off);
            int   oi = __shfl_down_sync(0xffffffffu, bi,   off);
            if (ov > best || (ov == best && oi < bi)) { best = ov; bi = oi; }
        }
        if (lane == 0) { rv[warp] = best; ri[warp] = bi; }
        __syncthreads();
        if (warp == 0) {
            float v = rv[lane]; int i2 = ri[lane];
            #pragma unroll
            for (int off = 16; off; off >>= 1) {
                float ov = __shfl_down_sync(0xffffffffu, v,  off);
                int   oi = __shfl_down_sync(0xffffffffu, i2, off);
                if (ov > v || (ov == v && oi < i2)) { v = ov; i2 = oi; }
            }
            if (lane == 0) s_last = i2;
        }
        __syncthreads();
        last = s_last;
    }
}

// ---------------- 2) GEMM: h = features @ W + b  (65536x512, K=256) ----------
// 64x64 tile, 256 threads, 4x4 microtile, float4 smem reads
__global__ void k_gemm1(const float* __restrict__ A, const float* __restrict__ W,
                        const float* __restrict__ bias) {
    __shared__ __align__(16) float As[16][68];
    __shared__ __align__(16) float Bs[16][68];

    const int tid = threadIdx.x;
    const int tx = tid & 15, ty = tid >> 4;
    const int m0 = blockIdx.y * 64;
    const int n0 = blockIdx.x * 64;

    const int am = tid >> 2;            // 0..63
    const int ak = (tid & 3) * 4;       // 0,4,8,12
    const int bk = tid >> 4;            // 0..15
    const int bn = (tid & 15) * 4;      // 0..60

    float acc[4][4] = {};

    for (int k0 = 0; k0 < FIN; k0 += 16) {
        float4 av = *(const float4*)&A[(size_t)(m0 + am)*FIN + k0 + ak];
        float4 bv = *(const float4*)&W[(size_t)(k0 + bk)*FOUT + n0 + bn];
        __syncthreads();
        As[ak+0][am] = av.x; As[ak+1][am] = av.y;
        As[ak+2][am] = av.z; As[ak+3][am] = av.w;
        *(float4*)&Bs[bk][bn] = bv;
        __syncthreads();
        #pragma unroll
        for (int k = 0; k < 16; k++) {
            float4 a4 = *(const float4*)&As[k][ty*4];
            float4 b4 = *(const float4*)&Bs[k][tx*4];
            acc[0][0] += a4.x*b4.x; acc[0][1] += a4.x*b4.y; acc[0][2] += a4.x*b4.z; acc[0][3] += a4.x*b4.w;
            acc[1][0] += a4.y*b4.x; acc[1][1] += a4.y*b4.y; acc[1][2] += a4.y*b4.z; acc[1][3] += a4.y*b4.w;
            acc[2][0] += a4.z*b4.x; acc[2][1] += a4.z*b4.y; acc[2][2] += a4.z*b4.z; acc[2][3] += a4.z*b4.w;
            acc[3][0] += a4.w*b4.x; acc[3][1] += a4.w*b4.y; acc[3][2] += a4.w*b4.z; acc[3][3] += a4.w*b4.w;
        }
    }
    #pragma unroll
    for (int i = 0; i < 4; i++) {
        int m = m0 + ty*4 + i;
        int n = n0 + tx*4;
        float4 o;
        o.x = acc[i][0] + bias[n+0];
        o.y = acc[i][1] + bias[n+1];
        o.z = acc[i][2] + bias[n+2];
        o.w = acc[i][3] + bias[n+3];
        *(float4*)&g_h[(size_t)m*FOUT + n] = o;
    }
}

// ---------------- 3) batchnorm stats: deterministic two-pass ----------------
__global__ void k_stats() {
    const int blk = blockIdx.x;        // 256 blocks x 256 rows
    const int t   = threadIdx.x;       // 256 threads, cols t and t+256
    const float* base = g_h + (size_t)blk * 256 * FOUT;
    float s0=0.f, s1=0.f, q0=0.f, q1=0.f;
    for (int r = 0; r < 256; r++) {
        float a = base[(size_t)r*FOUT + t];
        float c = base[(size_t)r*FOUT + t + 256];
        s0 += a; q0 += a*a; s1 += c; q1 += c*c;
    }
    g_psum[blk*FOUT + t]       = s0;
    g_psum[blk*FOUT + t + 256] = s1;
    g_psq [blk*FOUT + t]       = q0;
    g_psq [blk*FOUT + t + 256] = q1;
}

__global__ void k_finalize() {
    const int c = threadIdx.x;   // 512
    float s = 0.f, q = 0.f;
    for (int i = 0; i < 256; i++) { s += g_psum[i*FOUT + c]; q += g_psq[i*FOUT + c]; }
    float mu  = s * (1.0f / NTOT);
    float var = q * (1.0f / NTOT) - mu*mu;
    g_mu[c]   = mu;
    g_rsig[c] = rsqrtf(var + 1e-5f);
}

// ---------------- 4) ||x||^2 per point, feature space ----------------
__global__ void k_xnorm(const float* __restrict__ feat) {
    const int lane = threadIdx.x & 31;
    const int p = blockIdx.x * 8 + (threadIdx.x >> 5);
    const float4* fp = (const float4*)(feat + (size_t)p * FIN);
    float4 v1 = fp[lane*2], v2 = fp[lane*2 + 1];
    float s = v1.x*v1.x + v1.y*v1.y + v1.z*v1.z + v1.w*v1.w
            + v2.x*v2.x + v2.y*v2.y + v2.z*v2.z + v2.w*v2.w;
    #pragma unroll
    for (int off = 16; off; off >>= 1) s += __shfl_down_sync(0xffffffffu, s, off);
    if (lane == 0) g_xnorm[p] = s;
}

// ---------------- 5) KNN: per (cloud, 32-query group) ----------------
// dist = ||x||^2 - 2 q.x  (||q||^2 is rank-invariant per query row)
#define QS(k,q) Qs[(k)*33 + (q)]
#define XS(k,c) Xs[(k)*68 + (c)]
#define DS(q,c) Ds[(q)*68 + (c)]
__global__ void k_knn(const float* __restrict__ feat) {
    extern __shared__ __align__(16) char sm[];
    float* Qs   = (float*)(sm);              // [256][33]  33792 B
    float* Xs   = (float*)(sm + 33792);      // [16][68]   4352 B
    float* Ds   = (float*)(sm + 38144);      // [32][68]   8704 B
    float* topd = (float*)(sm + 46848);      // [32][16]   2048 B
    int*   topi = (int*)  (sm + 48896);      // [32][16]   2048 B
    float* wd   = (float*)(sm + 50944);      // [32]
    int*   wp   = (int*)  (sm + 51072);      // [32]  -> total 51200

    const int qg  = blockIdx.x;       // 0..31
    const int b   = blockIdx.y;       // 0..15
    const int tid = threadIdx.x;      // 256
    const float* fb = feat + (size_t)b * NP * FIN;

    for (int idx = tid; idx < 32*FIN; idx += 256) {
        int qi = idx >> 8, k = idx & 255;
        int g = g_fps[b*NS + qg*32 + qi];
        QS(k, qi) = feat[(size_t)g * FIN + k];
    }
    if (tid < 32) {
        wd[tid] = finf(); wp[tid] = 0;
        for (int j = 0; j < NK; j++) { topd[tid*NK + j] = finf(); topi[tid*NK + j] = 0; }
    }
    __syncthreads();

    const int tx = tid & 15, ty = tid >> 4;
    const int lc = tid >> 2;            // 0..63
    const int lk = (tid & 3) * 4;       // 0,4,8,12

    for (int c0 = 0; c0 < NP; c0 += 64) {
        float acc0[4] = {}, acc1[4] = {};
        for (int kt = 0; kt < FIN; kt += 16) {
            float4 xv = *(const float4*)&fb[(size_t)(c0 + lc)*FIN + kt + lk];
            __syncthreads();
            XS(lk+0, lc) = xv.x; XS(lk+1, lc) = xv.y;
            XS(lk+2, lc) = xv.z; XS(lk+3, lc) = xv.w;
            __syncthreads();
            #pragma unroll
            for (int k = 0; k < 16; k++) {
                float a0 = QS(kt + k, ty);
                float a1 = QS(kt + k, ty + 16);
                float4 b4 = *(const float4*)&XS(k, tx*4);
                acc0[0] += a0*b4.x; acc0[1] += a0*b4.y; acc0[2] += a0*b4.z; acc0[3] += a0*b4.w;
                acc1[0] += a1*b4.x; acc1[1] += a1*b4.y; acc1[2] += a1*b4.z; acc1[3] += a1*b4.w;
            }
        }
        #pragma unroll
        for (int j = 0; j < 4; j++) {
            int c = tx*4 + j;
            float xn = g_xnorm[b*NP + c0 + c];
            DS(ty,      c) = fmaf(-2.0f, acc0[j], xn);
            DS(ty + 16, c) = fmaf(-2.0f, acc1[j], xn);
        }
        __syncthreads();
        if (tid < 32) {
            const int qi = tid;
            float w = wd[qi]; int wpos = wp[qi];
            for (int c = 0; c < 64; c++) {
                float d = DS(qi, c);
                if (d < w) {                       // strict < : earliest index wins ties
                    topd[qi*NK + wpos] = d; topi[qi*NK + wpos] = c0 + c;
                    w = topd[qi*NK]; wpos = 0;
                    #pragma unroll
                    for (int j = 1; j < NK; j++)
                        if (topd[qi*NK + j] > w) { w = topd[qi*NK + j]; wpos = j; }
                }
            }
            wd[qi] = w; wp[qi] = wpos;
        }
        __syncthreads();
    }

    for (int idx = tid; idx < 32*NK; idx += 256) {
        int qi = idx / NK, j = idx - qi*NK;
        g_knn[(b*NS + qg*32 + qi)*NK + j] = b*NP + topi[qi*NK + j];
    }
}

// ---------------- 6) gather + affine norm + relu + max-pool ----------------
__global__ void k_pool(const float* __restrict__ gamma, const float* __restrict__ beta,
                       float* __restrict__ out) {
    const int r = blockIdx.x;      // 16384
    const int t = threadIdx.x;     // 128, cols t + i*128
    __shared__ int nb[NK];
    if (t < NK) nb[t] = g_knn[r*NK + t];
    __syncthreads();
    float a[4], c[4], m[4];
    #pragma unroll
    for (int i = 0; i < 4; i++) {
        int col = t + i*128;
        float aa = gamma[col] * g_rsig[col];
        a[i] = aa;
        c[i] = beta[col] - aa * g_mu[col];
        m[i] = -finf();
    }
    for (int j = 0; j < NK; j++) {
        const float* hr = g_h + (size_t)nb[j] * FOUT;
        #pragma unroll
        for (int i = 0; i < 4; i++)
            m[i] = fmaxf(m[i], fmaf(a[i], hr[t + i*128], c[i]));
    }
    #pragma unroll
    for (int i = 0; i < 4; i++)
        out[(size_t)r*FOUT + t + i*128] = fmaxf(m[i], 0.0f);
}

// ---------------- 7) fps positions + batch outputs ----------------
__global__ void k_meta(const float* __restrict__ pos,
                       float* __restrict__ out_pos, float* __restrict__ out_batch) {
    const int r = blockIdx.x * 1024 + threadIdx.x;   // 16 x 1024
    int g = g_fps[r];
    if (out_pos) {
        out_pos[r*3 + 0] = pos[(size_t)g*3 + 0];
        out_pos[r*3 + 1] = pos[(size_t)g*3 + 1];
        out_pos[r*3 + 2] = pos[(size_t)g*3 + 2];
    }
    if (out_batch) out_batch[r] = (float)(g >> 12);   // g / NP
}

// ---------------- launch ----------------
extern "C" void kernel_launch(void* const* d_in, const int* in_sizes, int n_in,
                              void* d_out, int out_size) {
    const float* features  = (const float*)d_in[0];
    const float* positions = (const float*)d_in[1];
    const float* W     = (const float*)d_in[3];
    const float* bias  = (const float*)d_in[4];
    const float* gamma = (const float*)d_in[5];
    const float* beta  = (const float*)d_in[6];
    float* out = (float*)d_out;

    cudaFuncSetAttribute(k_fps, cudaFuncAttributeMaxDynamicSharedMemorySize, 49152);
    cudaFuncSetAttribute(k_knn, cudaFuncAttributeMaxDynamicSharedMemorySize, 51200);

    const long NFE = (long)NQ * FOUT;                 // 8388608
    float* out_pos   = (out_size >= NFE + NQ*3)        ? out + NFE          : nullptr;
    float* out_batch = (out_size >= NFE + NQ*3 + NQ)   ? out + NFE + NQ*3   : nullptr;

    k_fps   <<<NB, 1024, 49152>>>(positions);
    k_gemm1 <<<dim3(FOUT/64, NTOT/64), 256>>>(features, W, bias);
    k_stats <<<256, 256>>>();
    k_finalize<<<1, FOUT>>>();
    k_xnorm <<<NTOT/8, 256>>>(features);
    k_knn   <<<dim3(NS/32, NB), 256, 51200>>>(features);
    k_pool  <<<NQ, 128>>>(gamma, beta, out);
    k_meta  <<<NB, 1024>>>(positions, out_pos, out_batch);
}

// round 4
// speedup vs baseline: 1.1992x; 1.1992x over previous
#include <cuda_runtime.h>
#include <math.h>

#define NB   16
#define NP   4096
#define NS   1024
#define NK   16
#define NK2  32      // approx top-32 window
#define FIN  256
#define FOUT 512
#define NTOT (NB*NP)   // 65536
#define NQ   (NB*NS)   // 16384

// ---------------- device scratch (allocation-free) ----------------
__device__ float g_h[NTOT*FOUT];        // 134 MB pre-norm MLP output
__device__ float g_xnorm[NTOT];         // ||x||^2 per point (feature space)
__device__ int   g_fps[NQ];             // global fps indices
__device__ int   g_knn32[NQ*NK2];       // approx top-32 candidate indices
__device__ int   g_knn[NQ*NK];          // final knn indices
__device__ float g_psum[256*FOUT];      // partial column sums
__device__ float g_psq [256*FOUT];      // partial column sumsq
__device__ float g_mu  [FOUT];
__device__ float g_rsig[FOUT];

__device__ __forceinline__ float finf() { return __int_as_float(0x7f800000); }

// tf32 mma helper: D += A*B, m16n8k8
__device__ __forceinline__ void mma8(float (&d)[4], unsigned a0, unsigned a1,
                                     unsigned a2, unsigned a3,
                                     unsigned b0, unsigned b1) {
    asm volatile(
        "mma.sync.aligned.m16n8k8.row.col.f32.tf32.tf32.f32 "
        "{%0,%1,%2,%3},{%4,%5,%6,%7},{%8,%9},{%0,%1,%2,%3};"
        : "+f"(d[0]), "+f"(d[1]), "+f"(d[2]), "+f"(d[3])
        : "r"(a0), "r"(a1), "r"(a2), "r"(a3), "r"(b0), "r"(b1));
}

// split fp32 -> tf32-exact hi + residual lo (hi has 10 explicit mantissa bits)
__device__ __forceinline__ void split2(unsigned v, unsigned& hi, unsigned& lo) {
    hi = v & 0xFFFFE000u;
    lo = __float_as_uint(__uint_as_float(v) - __uint_as_float(hi));
}

// ---------------- 1) farthest point sampling ----------------
__global__ void k_fps(const float* __restrict__ pos) {
    extern __shared__ float sp[];          // px[4096] py[4096] pz[4096] = 48KB
    float* px = sp; float* py = sp + NP; float* pz = sp + 2*NP;
    __shared__ float rv[32];
    __shared__ int   ri[32];
    __shared__ int   s_last;

    const int b   = blockIdx.x;
    const int tid = threadIdx.x;
    const int lane = tid & 31, warp = tid >> 5;
    const float* pb = pos + (size_t)b * NP * 3;

    for (int i = tid; i < NP*3; i += 1024) {
        float v = pb[i];
        int p = i / 3, d = i - p*3;
        if (d == 0) px[p] = v; else if (d == 1) py[p] = v; else pz[p] = v;
    }
    __syncthreads();

    float md[4] = {finf(), finf(), finf(), finf()};
    int last = 0;

    for (int s = 0; s < NS; s++) {
        if (tid == 0) g_fps[b*NS + s] = b*NP + last;
        float qx = px[last], qy = py[last], qz = pz[last];

        float best = -finf(); int bi = 0;
        #pragma unroll
        for (int j = 0; j < 4; j++) {
            int p = tid + j*1024;
            float dx = px[p]-qx, dy = py[p]-qy, dz = pz[p]-qz;
            float d = dx*dx + dy*dy + dz*dz;
            float m = fminf(md[j], d);
            md[j] = m;
            if (m > best) { best = m; bi = p; }
        }
        #pragma unroll
        for (int off = 16; off; off >>= 1) {
            float ov = __shfl_down_sync(0xffffffffu, best, off);
            int   oi = __shfl_down_sync(0xffffffffu, bi,   off);
            if (ov > best || (ov == best && oi < bi)) { best = ov; bi = oi; }
        }
        if (lane == 0) { rv[warp] = best; ri[warp] = bi; }
        __syncthreads();
        if (warp == 0) {
            float v = rv[lane]; int i2 = ri[lane];
            #pragma unroll
            for (int off = 16; off; off >>= 1) {
                float ov = __shfl_down_sync(0xffffffffu, v,  off);
                int   oi = __shfl_down_sync(0xffffffffu, i2, off);
                if (ov > v || (ov == v && oi < i2)) { v = ov; i2 = oi; }
            }
            if (lane == 0) s_last = i2;
        }
        __syncthreads();
        last = s_last;
    }
}

// ---------------- 2) GEMM: h = features @ W + b  (3xTF32 tensor-core) --------
// 64x64 tile, BK=32, 256 threads = 8 warps (4m x 2n), warp tile 16x32
__global__ void k_gemm1(const float* __restrict__ A, const float* __restrict__ W,
                        const float* __restrict__ bias) {
    __shared__ __align__(16) float As[64*36];
    __shared__ __align__(16) float Bs[32*72];

    const int tid = threadIdx.x;
    const int m0 = blockIdx.y * 64, n0 = blockIdx.x * 64;
    const int warp = tid >> 5, lane = tid & 31;
    const int wm = warp >> 1, wn = warp & 1;
    const int r = lane >> 2, c = lane & 3;
    const int arow = tid >> 2, acol = (tid & 3) * 8;
    const int brow = tid >> 3, bcol = (tid & 7) * 8;

    unsigned* AsU = (unsigned*)As;
    unsigned* BsU = (unsigned*)Bs;
    float acc[4][4] = {};

    for (int k0 = 0; k0 < FIN; k0 += 32) {
        float4 a0 = *(const float4*)&A[(size_t)(m0+arow)*FIN + k0 + acol];
        float4 a1 = *(const float4*)&A[(size_t)(m0+arow)*FIN + k0 + acol + 4];
        float4 b0 = *(const float4*)&W[(size_t)(k0+brow)*FOUT + n0 + bcol];
        float4 b1 = *(const float4*)&W[(size_t)(k0+brow)*FOUT + n0 + bcol + 4];
        __syncthreads();
        *(float4*)&As[arow*36 + acol]     = a0;
        *(float4*)&As[arow*36 + acol + 4] = a1;
        *(float4*)&Bs[brow*72 + bcol]     = b0;
        *(float4*)&Bs[brow*72 + bcol + 4] = b1;
        __syncthreads();
        #pragma unroll
        for (int k8 = 0; k8 < 4; k8++) {
            const int kk = k8 * 8;
            unsigned av0 = AsU[(wm*16 + r    )*36 + kk + c];
            unsigned av1 = AsU[(wm*16 + r + 8)*36 + kk + c];
            unsigned av2 = AsU[(wm*16 + r    )*36 + kk + c + 4];
            unsigned av3 = AsU[(wm*16 + r + 8)*36 + kk + c + 4];
            unsigned ah0,al0,ah1,al1,ah2,al2,ah3,al3;
            split2(av0, ah0, al0); split2(av1, ah1, al1);
            split2(av2, ah2, al2); split2(av3, ah3, al3);
            #pragma unroll
            for (int t = 0; t < 4; t++) {
                const int n = wn*32 + t*8 + r;
                unsigned bv0 = BsU[(kk + c    )*72 + n];
                unsigned bv1 = BsU[(kk + c + 4)*72 + n];
                unsigned bh0,bl0,bh1,bl1;
                split2(bv0, bh0, bl0); split2(bv1, bh1, bl1);
                mma8(acc[t], ah0,ah1,ah2,ah3, bh0,bh1);
                mma8(acc[t], ah0,ah1,ah2,ah3, bl0,bl1);
                mma8(acc[t], al0,al1,al2,al3, bh0,bh1);
            }
        }
    }
    #pragma unroll
    for (int t = 0; t < 4; t++) {
        const int col = n0 + wn*32 + t*8 + 2*c;
        const int row = m0 + wm*16 + r;
        float2 o0, o1;
        o0.x = acc[t][0] + bias[col];   o0.y = acc[t][1] + bias[col+1];
        o1.x = acc[t][2] + bias[col];   o1.y = acc[t][3] + bias[col+1];
        *(float2*)&g_h[(size_t)row*FOUT + col]     = o0;
        *(float2*)&g_h[(size_t)(row+8)*FOUT + col] = o1;
    }
}

// ---------------- 3) batchnorm stats: deterministic two-pass ----------------
__global__ void k_stats() {
    const int blk = blockIdx.x;        // 256 blocks x 256 rows
    const int t   = threadIdx.x;
    const float* base = g_h + (size_t)blk * 256 * FOUT;
    float s0=0.f, s1=0.f, q0=0.f, q1=0.f;
    for (int r = 0; r < 256; r++) {
        float a = base[(size_t)r*FOUT + t];
        float c = base[(size_t)r*FOUT + t + 256];
        s0 += a; q0 += a*a; s1 += c; q1 += c*c;
    }
    g_psum[blk*FOUT + t]       = s0;
    g_psum[blk*FOUT + t + 256] = s1;
    g_psq [blk*FOUT + t]       = q0;
    g_psq [blk*FOUT + t + 256] = q1;
}

__global__ void k_finalize() {
    // 8 blocks x 512 threads; 64 cols per block, 8 threads per col
    const int tid = threadIdx.x;
    const int col = blockIdx.x * 64 + (tid >> 3);
    const int part = tid & 7;
    float s = 0.f, q = 0.f;
    for (int i = part; i < 256; i += 8) {
        s += g_psum[i*FOUT + col];
        q += g_psq [i*FOUT + col];
    }
    #pragma unroll
    for (int off = 4; off; off >>= 1) {
        s += __shfl_down_sync(0xffffffffu, s, off);
        q += __shfl_down_sync(0xffffffffu, q, off);
    }
    if (part == 0) {
        float mu  = s * (1.0f / NTOT);
        float var = q * (1.0f / NTOT) - mu*mu;
        g_mu[col]   = mu;
        g_rsig[col] = rsqrtf(var + 1e-5f);
    }
}

// ---------------- 4) ||x||^2 per point, feature space ----------------
__global__ void k_xnorm(const float* __restrict__ feat) {
    const int lane = threadIdx.x & 31;
    const int p = blockIdx.x * 8 + (threadIdx.x >> 5);
    const float4* fp = (const float4*)(feat + (size_t)p * FIN);
    float4 v1 = fp[lane*2], v2 = fp[lane*2 + 1];
    float s = v1.x*v1.x + v1.y*v1.y + v1.z*v1.z + v1.w*v1.w
            + v2.x*v2.x + v2.y*v2.y + v2.z*v2.z + v2.w*v2.w;
    #pragma unroll
    for (int off = 16; off; off >>= 1) s += __shfl_down_sync(0xffffffffu, s, off);
    if (lane == 0) g_xnorm[p] = s;
}

// ---------------- 5) KNN approx top-32 via tf32 mma ----------------
// block = 256 threads (8 warps: 2 q-halves x 4 cand-quarters)
// 32 queries x 128-candidate chunks; K=256 in 64-chunks
// smem byte offsets:
//  Qs   [32][260]f : 0      (33280)
//  Xs   [128][68]f : 33280  (34816)
//  Ds   [32][132]f : 68096  (16896)
//  sxn  [128]f     : 84992  (512)
//  topd [32][32]f  : 85504  (4096)
//  topi [32][32]i  : 89600  (4096)
//  wd   [32]f      : 93696
//  wp   [32]i      : 93824
//  cnt  [32]i      : 93952
//  buf  [32][128]i : 94080  (16384) -> total 110464
#define KNN_SMEM 110464
__global__ void k_knn(const float* __restrict__ feat) {
    extern __shared__ __align__(16) char sm[];
    float* Qs   = (float*)(sm);
    float* Xs   = (float*)(sm + 33280);
    float* Ds   = (float*)(sm + 68096);
    float* sxn  = (float*)(sm + 84992);
    float* topd = (float*)(sm + 85504);
    int*   topi = (int*)  (sm + 89600);
    float* wd   = (float*)(sm + 93696);
    int*   wp   = (int*)  (sm + 93824);
    int*   cnt  = (int*)  (sm + 93952);
    int*   buf  = (int*)  (sm + 94080);

    const int qg  = blockIdx.x;       // 0..31
    const int b   = blockIdx.y;       // 0..15
    const int tid = threadIdx.x;      // 256
    const float* fb = feat + (size_t)b * NP * FIN;

    // load Q tile (raw fp32; HW truncates to tf32 -> approx ranking only)
    for (int i = tid; i < 32*64; i += 256) {
        int q = i >> 6, c4 = (i & 63) * 4;
        int g = g_fps[b*NS + qg*32 + q];
        *(float4*)&Qs[q*260 + c4] = *(const float4*)&feat[(size_t)g*FIN + c4];
    }
    if (tid < 32) {
        wd[tid] = finf(); wp[tid] = 0;
        for (int j = 0; j < NK2; j++) { topd[tid*NK2 + j] = finf(); topi[tid*NK2 + j] = 0; }
    }
    __syncthreads();

    const int warp = tid >> 5, lane = tid & 31;
    const int wy = warp & 1, wx = warp >> 1;
    const int r = lane >> 2, c = lane & 3;
    unsigned* QsU = (unsigned*)Qs;
    unsigned* XsU = (unsigned*)Xs;

    for (int c0 = 0; c0 < NP; c0 += 128) {
        float acc[4][4] = {};
        for (int kt = 0; kt < FIN; kt += 64) {
            __syncthreads();   // previous mma reads of Xs complete
            for (int i = tid; i < 128*16; i += 256) {
                int row = i >> 4, c4 = (i & 15) * 4;
                *(float4*)&Xs[row*68 + c4] =
                    *(const float4*)&fb[(size_t)(c0+row)*FIN + kt + c4];
            }
            if (kt == 0 && tid < 128) sxn[tid] = g_xnorm[b*NP + c0 + tid];
            __syncthreads();
            #pragma unroll
            for (int k8 = 0; k8 < 8; k8++) {
                const int kk = k8 * 8;
                const int kq = kt + kk;
                unsigned a0 = QsU[(wy*16 + r    )*260 + kq + c];
                unsigned a1 = QsU[(wy*16 + r + 8)*260 + kq + c];
                unsigned a2 = QsU[(wy*16 + r    )*260 + kq + c + 4];
                unsigned a3 = QsU[(wy*16 + r + 8)*260 + kq + c + 4];
                #pragma unroll
                for (int t = 0; t < 4; t++) {
                    const int n = wx*32 + t*8 + r;
                    unsigned b0 = XsU[n*68 + kk + c];
                    unsigned b1 = XsU[n*68 + kk + c + 4];
                    mma8(acc[t], a0,a1,a2,a3, b0,b1);
                }
            }
        }
        // distances into Ds
        #pragma unroll
        for (int t = 0; t < 4; t++) {
            const int n0 = wx*32 + t*8 + 2*c;
            Ds[(wy*16 + r    )*132 + n0    ] = fmaf(-2.f, acc[t][0], sxn[n0]);
            Ds[(wy*16 + r    )*132 + n0 + 1] = fmaf(-2.f, acc[t][1], sxn[n0+1]);
            Ds[(wy*16 + r + 8)*132 + n0    ] = fmaf(-2.f, acc[t][2], sxn[n0]);
            Ds[(wy*16 + r + 8)*132 + n0 + 1] = fmaf(-2.f, acc[t][3], sxn[n0+1]);
        }
        if (tid < 32) cnt[tid] = 0;
        __syncthreads();
        // phase 1: cooperative threshold filter
        for (int i = tid; i < 32*128; i += 256) {
            int q = i >> 7, cc = i & 127;
            float d = Ds[q*132 + cc];
            if (d < wd[q]) { int p = atomicAdd(&cnt[q], 1); buf[q*128 + p] = cc; }
        }
        __syncthreads();
        // phase 2: serial insert of survivors (one thread per query)
        if (tid < 32) {
            const int q = tid;
            float w = wd[q]; int wpos = wp[q]; const int n = cnt[q];
            for (int j = 0; j < n; j++) {
                int cc = buf[q*128 + j];
                float d = Ds[q*132 + cc];
                if (d < w) {
                    topd[q*NK2 + wpos] = d; topi[q*NK2 + wpos] = c0 + cc;
                    w = topd[q*NK2]; wpos = 0;
                    #pragma unroll 4
                    for (int j2 = 1; j2 < NK2; j2++) {
                        float tv = topd[q*NK2 + j2];
                        if (tv > w) { w = tv; wpos = j2; }
                    }
                }
            }
            wd[q] = w; wp[q] = wpos;
        }
        __syncthreads();
    }

    for (int i = tid; i < 32*NK2; i += 256) {
        int q = i >> 5, j = i & 31;
        g_knn32[(b*NS + qg*32 + q)*NK2 + j] = b*NP + topi[q*NK2 + j];
    }
}

// ---------------- 5b) exact fp32 rescore: top-32 -> true top-16 ----------------
__global__ void k_rescore(const float* __restrict__ feat) {
    __shared__ float sdist[NK2];
    __shared__ int   sgid[NK2];
    const int q   = blockIdx.x;       // 0..16383
    const int tid = threadIdx.x;      // 256
    const int cidx = tid >> 3;        // candidate 0..31
    const int seg  = tid & 7;         // k segment
    const int gq = g_fps[q];
    const int gc = g_knn32[q*NK2 + cidx];
    const float4* qp = (const float4*)(feat + (size_t)gq * FIN);
    const float4* xp = (const float4*)(feat + (size_t)gc * FIN);
    float s = 0.f;
    #pragma unroll
    for (int i = 0; i < 8; i++) {
        float4 qv = qp[seg*8 + i];
        float4 xv = xp[seg*8 + i];
        s += qv.x*xv.x + qv.y*xv.y + qv.z*xv.z + qv.w*xv.w;
    }
    s += __shfl_down_sync(0xffffffffu, s, 4);
    s += __shfl_down_sync(0xffffffffu, s, 2);
    s += __shfl_down_sync(0xffffffffu, s, 1);
    if (seg == 0) { sdist[cidx] = fmaf(-2.f, s, g_xnorm[gc]); sgid[cidx] = gc; }
    __syncthreads();
    if (tid == 0) {
        #pragma unroll 1
        for (int j = 0; j < NK; j++) {
            float best = finf(); int bi = 0x7fffffff, bp = 0;
            for (int c2 = 0; c2 < NK2; c2++) {
                float d = sdist[c2]; int g = sgid[c2];
                if (d < best || (d == best && g < bi)) { best = d; bi = g; bp = c2; }
            }
            g_knn[q*NK + j] = bi;
            sdist[bp] = finf();
        }
    }
}

// ---------------- 6) gather + affine norm + relu + max-pool ----------------
__global__ void k_pool(const float* __restrict__ gamma, const float* __restrict__ beta,
                       float* __restrict__ out) {
    const int r = blockIdx.x;      // 16384
    const int t = threadIdx.x;     // 128
    __shared__ int nb[NK];
    if (t < NK) nb[t] = g_knn[r*NK + t];
    __syncthreads();
    float a[4], c[4], m[4];
    #pragma unroll
    for (int i = 0; i < 4; i++) {
        int col = t + i*128;
        float aa = gamma[col] * g_rsig[col];
        a[i] = aa;
        c[i] = beta[col] - aa * g_mu[col];
        m[i] = -finf();
    }
    for (int j = 0; j < NK; j++) {
        const float* hr = g_h + (size_t)nb[j] * FOUT;
        #pragma unroll
        for (int i = 0; i < 4; i++)
            m[i] = fmaxf(m[i], fmaf(a[i], hr[t + i*128], c[i]));
    }
    #pragma unroll
    for (int i = 0; i < 4; i++)
        out[(size_t)r*FOUT + t + i*128] = fmaxf(m[i], 0.0f);
}

// ---------------- 7) fps positions + batch outputs ----------------
__global__ void k_meta(const float* __restrict__ pos,
                       float* __restrict__ out_pos, float* __restrict__ out_batch) {
    const int r = blockIdx.x * 1024 + threadIdx.x;
    int g = g_fps[r];
    if (out_pos) {
        out_pos[r*3 + 0] = pos[(size_t)g*3 + 0];
        out_pos[r*3 + 1] = pos[(size_t)g*3 + 1];
        out_pos[r*3 + 2] = pos[(size_t)g*3 + 2];
    }
    if (out_batch) out_batch[r] = (float)(g >> 12);
}

// ---------------- launch ----------------
extern "C" void kernel_launch(void* const* d_in, const int* in_sizes, int n_in,
                              void* d_out, int out_size) {
    const float* features  = (const float*)d_in[0];
    const float* positions = (const float*)d_in[1];
    const float* W     = (const float*)d_in[3];
    const float* bias  = (const float*)d_in[4];
    const float* gamma = (const float*)d_in[5];
    const float* beta  = (const float*)d_in[6];
    float* out = (float*)d_out;

    cudaFuncSetAttribute(k_fps, cudaFuncAttributeMaxDynamicSharedMemorySize, 49152);
    cudaFuncSetAttribute(k_knn, cudaFuncAttributeMaxDynamicSharedMemorySize, KNN_SMEM);

    const long NFE = (long)NQ * FOUT;
    float* out_pos   = (out_size >= NFE + NQ*3)      ? out + NFE        : nullptr;
    float* out_batch = (out_size >= NFE + NQ*3 + NQ) ? out + NFE + NQ*3 : nullptr;

    k_fps     <<<NB, 1024, 49152>>>(positions);
    k_gemm1   <<<dim3(FOUT/64, NTOT/64), 256>>>(features, W, bias);
    k_stats   <<<256, 256>>>();
    k_finalize<<<8, 512>>>();
    k_xnorm   <<<NTOT/8, 256>>>(features);
    k_knn     <<<dim3(NS/32, NB), 256, KNN_SMEM>>>(features);
    k_rescore <<<NQ, 256>>>(features);
    k_pool    <<<NQ, 128>>>(gamma, beta, out);
    k_meta    <<<NB, 1024>>>(positions, out_pos, out_batch);
}

// round 8
// speedup vs baseline: 1.2401x; 1.0342x over previous
#include <cuda_runtime.h>
#include <cuda_bf16.h>
#include <math.h>
#include <stdint.h>

#define NB   16
#define NP   4096
#define NS   1024
#define NK   16
#define NK2  32
#define FIN  256
#define FOUT 512
#define NTOT (NB*NP)   // 65536
#define NQ   (NB*NS)   // 16384

// ---------------- device scratch ----------------
__device__ float          g_h[(size_t)NTOT*FOUT];
__device__ __nv_bfloat16  g_fhi[(size_t)NTOT*FIN];
__device__ float g_xnorm[NTOT];
__device__ int   g_fps[NQ];
__device__ int   g_knn32[NQ*NK2];
__device__ int   g_knn[NQ*NK];
__device__ float g_psum[256*FOUT];
__device__ float g_psq [256*FOUT];
__device__ float g_mu  [FOUT];
__device__ float g_rsig[FOUT];

__device__ __forceinline__ float finf() { return __int_as_float(0x7f800000); }

// bf16 mma: D += A(16x16) * B(16x8), fp32 accum
__device__ __forceinline__ void mma16(float (&d)[4], unsigned a0, unsigned a1,
                                      unsigned a2, unsigned a3,
                                      unsigned b0, unsigned b1) {
    asm volatile(
        "mma.sync.aligned.m16n8k16.row.col.f32.bf16.bf16.f32 "
        "{%0,%1,%2,%3},{%4,%5,%6,%7},{%8,%9},{%0,%1,%2,%3};"
        : "+f"(d[0]), "+f"(d[1]), "+f"(d[2]), "+f"(d[3])
        : "r"(a0), "r"(a1), "r"(a2), "r"(a3), "r"(b0), "r"(b1));
}

__device__ __forceinline__ unsigned bpack(__nv_bfloat16 x, __nv_bfloat16 y) {
    __nv_bfloat162 t = __halves2bfloat162(x, y);
    return *reinterpret_cast<unsigned*>(&t);
}
__device__ __forceinline__ unsigned fpack(float x, float y) {
    __nv_bfloat162 t = __floats2bfloat162_rn(x, y);
    return *reinterpret_cast<unsigned*>(&t);
}

// fused kernel smem byte offsets (GEMM branch); A/B padded to 80B rows
#define GA_AH 0
#define GA_AL 10240
#define GA_BH 20480
#define GA_BL 25600
#define GA_BI 30720
#define FUSED_SMEM 49152

// ======================= fused: FPS | MLP-GEMM | CVT =======================
// grid: [0,16) FPS, [16, 16+4096) GEMM, [4112, 4368) CVT.  256 threads.
__global__ void k_fused(const float* __restrict__ feat, const float* __restrict__ pos,
                        const float* __restrict__ W, const float* __restrict__ bias) {
    extern __shared__ __align__(16) char sm[];
    const int bid = blockIdx.x;
    const int tid = threadIdx.x;
    const int lane = tid & 31, warp = tid >> 5;

    if (bid < 16) {
        // ---------------- FPS: one block per cloud ----------------
        float* px = (float*)sm; float* py = px + NP; float* pz = py + NP;
        __shared__ float rv[8];
        __shared__ int   ri[8];
        __shared__ int   s_last;
        const int b = bid;
        const float* pb = pos + (size_t)b * NP * 3;
        for (int i = tid; i < NP*3; i += 256) {
            float v = pb[i];
            int p = i / 3, d = i - p*3;
            if (d == 0) px[p] = v; else if (d == 1) py[p] = v; else pz[p] = v;
        }
        __syncthreads();
        float md[16];
        #pragma unroll
        for (int j = 0; j < 16; j++) md[j] = finf();
        int last = 0;
        for (int s = 0; s < NS; s++) {
            if (tid == 0) g_fps[b*NS + s] = b*NP + last;
            float qx = px[last], qy = py[last], qz = pz[last];
            float best = -finf(); int bi = 0;
            #pragma unroll
            for (int j = 0; j < 16; j++) {
                int p = tid + j*256;
                float dx = px[p]-qx, dy = py[p]-qy, dz = pz[p]-qz;
                float d = dx*dx + dy*dy + dz*dz;
                float m = fminf(md[j], d);
                md[j] = m;
                if (m > best) { best = m; bi = p; }
            }
            #pragma unroll
            for (int off = 16; off; off >>= 1) {
                float ov = __shfl_down_sync(0xffffffffu, best, off);
                int   oi = __shfl_down_sync(0xffffffffu, bi,   off);
                if (ov > best || (ov == best && oi < bi)) { best = ov; bi = oi; }
            }
            if (lane == 0) { rv[warp] = best; ri[warp] = bi; }
            __syncthreads();
            if (warp == 0) {
                float v = (lane < 8) ? rv[lane] : -finf();
                int i2 = (lane < 8) ? ri[lane] : 0x7fffffff;
                #pragma unroll
                for (int off = 4; off; off >>= 1) {
                    float ov = __shfl_down_sync(0xffffffffu, v,  off);
                    int   oi = __shfl_down_sync(0xffffffffu, i2, off);
                    if (ov > v || (ov == v && oi < i2)) { v = ov; i2 = oi; }
                }
                if (lane == 0) s_last = i2;
            }
            __syncthreads();
            last = s_last;
        }
        return;
    }

    if (bid < 16 + 4096) {
        // ------------- MLP GEMM: tile 128m x 64n, bf16x3, 8 warps -------------
        const int t  = bid - 16;
        const int m0 = (t >> 3) * 128;
        const int n0 = (t & 7) * 64;
        unsigned* AhU = (unsigned*)(sm + GA_AH);
        unsigned* AlU = (unsigned*)(sm + GA_AL);
        unsigned* BhU = (unsigned*)(sm + GA_BH);
        unsigned* BlU = (unsigned*)(sm + GA_BL);
        float*  sbias = (float*)(sm + GA_BI);

        if (tid < 64) sbias[tid] = bias[n0 + tid];

        const int wm = warp & 3, wn = warp >> 2;
        const int r = lane >> 2, c = lane & 3;
        float acc[2][4][4] = {};

        for (int kc = 0; kc < 8; kc++) {
            __syncthreads();
            // A: 128 rows x 32 k fp32 -> hi/lo bf16
            #pragma unroll
            for (int it = 0; it < 4; it++) {
                int idx = tid + it*256;            // 0..1023
                int row = idx >> 3, f4 = idx & 7;
                float4 v = *(const float4*)&feat[(size_t)(m0+row)*FIN + kc*32 + f4*4];
                __nv_bfloat16 h0 = __float2bfloat16(v.x), h1 = __float2bfloat16(v.y);
                __nv_bfloat16 h2 = __float2bfloat16(v.z), h3 = __float2bfloat16(v.w);
                uint2 hi = { bpack(h0,h1), bpack(h2,h3) };
                uint2 lo = { fpack(v.x - __bfloat162float(h0), v.y - __bfloat162float(h1)),
                             fpack(v.z - __bfloat162float(h2), v.w - __bfloat162float(h3)) };
                *(uint2*)((char*)AhU + row*80 + f4*8) = hi;
                *(uint2*)((char*)AlU + row*80 + f4*8) = lo;
            }
            // B: 32 k x 64 n, transposed store Bs[n][k]
            {
                const int n = tid & 63, kpb = tid >> 6;
                #pragma unroll
                for (int it = 0; it < 4; it++) {
                    int kp = kpb + it*4;           // 0..15
                    int k0 = kc*32 + 2*kp;
                    float w0 = W[(size_t)k0*FOUT + n0 + n];
                    float w1 = W[(size_t)(k0+1)*FOUT + n0 + n];
                    __nv_bfloat16 h0 = __float2bfloat16(w0), h1 = __float2bfloat16(w1);
                    *(unsigned*)((char*)BhU + n*80 + kp*4) = bpack(h0, h1);
                    *(unsigned*)((char*)BlU + n*80 + kp*4) =
                        fpack(w0 - __bfloat162float(h0), w1 - __bfloat162float(h1));
                }
            }
            __syncthreads();
            #pragma unroll
            for (int ks = 0; ks < 2; ks++) {
                const int ko = ks*8 + c;
                unsigned bh[4][2], bl[4][2];
                #pragma unroll
                for (int nf = 0; nf < 4; nf++) {
                    int n = wn*32 + nf*8 + r;
                    bh[nf][0] = BhU[n*20 + ko];     bh[nf][1] = BhU[n*20 + ko + 4];
                    bl[nf][0] = BlU[n*20 + ko];     bl[nf][1] = BlU[n*20 + ko + 4];
                }
                #pragma unroll
                for (int mf = 0; mf < 2; mf++) {
                    int mb = wm*32 + mf*16;
                    unsigned ah0 = AhU[(mb+r  )*20 + ko], ah1 = AhU[(mb+r+8)*20 + ko];
                    unsigned ah2 = AhU[(mb+r  )*20 + ko + 4], ah3 = AhU[(mb+r+8)*20 + ko + 4];
                    unsigned al0 = AlU[(mb+r  )*20 + ko], al1 = AlU[(mb+r+8)*20 + ko];
                    unsigned al2 = AlU[(mb+r  )*20 + ko + 4], al3 = AlU[(mb+r+8)*20 + ko + 4];
                    #pragma unroll
                    for (int nf = 0; nf < 4; nf++) {
                        mma16(acc[mf][nf], ah0,ah1,ah2,ah3, bh[nf][0], bh[nf][1]);
                        mma16(acc[mf][nf], ah0,ah1,ah2,ah3, bl[nf][0], bl[nf][1]);
                        mma16(acc[mf][nf], al0,al1,al2,al3, bh[nf][0], bh[nf][1]);
                    }
                }
            }
        }
        // epilogue
        #pragma unroll
        for (int mf = 0; mf < 2; mf++) {
            #pragma unroll
            for (int nf = 0; nf < 4; nf++) {
                int row = m0 + wm*32 + mf*16 + r;
                int coll = wn*32 + nf*8 + 2*c;
                float b0v = sbias[coll], b1v = sbias[coll+1];
                int col = n0 + coll;
                float2 o0 = { acc[mf][nf][0] + b0v, acc[mf][nf][1] + b1v };
                float2 o1 = { acc[mf][nf][2] + b0v, acc[mf][nf][3] + b1v };
                *(float2*)&g_h[(size_t)row*FOUT + col]     = o0;
                *(float2*)&g_h[(size_t)(row+8)*FOUT + col] = o1;
            }
        }
        return;
    }

    // ---------------- CVT: fp32 features -> bf16 g_fhi + xnorm ----------------
    {
        const int bidc = bid - (16 + 4096);   // 0..255, 256 rows each
        const int q = tid & 3;
        #pragma unroll 1
        for (int p = 0; p < 4; p++) {
            const int row = bidc*256 + p*64 + (tid >> 2);
            const float4* src = (const float4*)(feat + (size_t)row*FIN + q*64);
            uint4* dst = (uint4*)g_fhi + (size_t)row*32 + q*8;
            float s = 0.f;
            #pragma unroll
            for (int i = 0; i < 8; i++) {
                float4 a = src[2*i], b = src[2*i+1];
                s += a.x*a.x + a.y*a.y + a.z*a.z + a.w*a.w
                   + b.x*b.x + b.y*b.y + b.z*b.z + b.w*b.w;
                uint4 u;
                u.x = fpack(a.x, a.y); u.y = fpack(a.z, a.w);
                u.z = fpack(b.x, b.y); u.w = fpack(b.z, b.w);
                dst[i] = u;
            }
            s += __shfl_xor_sync(0xffffffffu, s, 1);
            s += __shfl_xor_sync(0xffffffffu, s, 2);
            if (q == 0) g_xnorm[row] = s;
        }
    }
}

// ======================= batchnorm stats =======================
__global__ void k_stats() {
    const int blk = blockIdx.x;
    const int t   = threadIdx.x;
    const float* base = g_h + (size_t)blk * 256 * FOUT;
    float s0=0.f, s1=0.f, q0=0.f, q1=0.f;
    for (int r = 0; r < 256; r++) {
        float a = base[(size_t)r*FOUT + t];
        float c = base[(size_t)r*FOUT + t + 256];
        s0 += a; q0 += a*a; s1 += c; q1 += c*c;
    }
    g_psum[blk*FOUT + t]       = s0;
    g_psum[blk*FOUT + t + 256] = s1;
    g_psq [blk*FOUT + t]       = q0;
    g_psq [blk*FOUT + t + 256] = q1;
}

__global__ void k_finalize() {
    const int tid = threadIdx.x;
    const int col = blockIdx.x * 64 + (tid >> 3);
    const int part = tid & 7;
    float s = 0.f, q = 0.f;
    for (int i = part; i < 256; i += 8) {
        s += g_psum[i*FOUT + col];
        q += g_psq [i*FOUT + col];
    }
    #pragma unroll
    for (int off = 4; off; off >>= 1) {
        s += __shfl_down_sync(0xffffffffu, s, off);
        q += __shfl_down_sync(0xffffffffu, q, off);
    }
    if (part == 0) {
        float mu  = s * (1.0f / NTOT);
        float var = q * (1.0f / NTOT) - mu*mu;
        g_mu[col]   = mu;
        g_rsig[col] = rsqrtf(var + 1e-5f);
    }
}

// ======================= KNN: bf16 mma, register top-16 per slice ============
// block: 64 queries x full cloud; chunks of 128 candidates, k-subchunks of 64.
// smem: Qs[64][264h] @0 (33792), Xs[128][72h] @33792 (18432),
//       Ds[64][133]f @52224 (34048), sxn[128]f @86272 (512) -> 86784
#define KQ_OFF 0
#define KX_OFF 33792
#define KD_OFF 52224
#define KS_OFF 86272
#define KNN_SMEM 86784
__global__ void k_knn() {
    extern __shared__ __align__(16) char sm[];
    unsigned* QsU = (unsigned*)(sm + KQ_OFF);
    unsigned* XsU = (unsigned*)(sm + KX_OFF);
    float*    Ds  = (float*)(sm + KD_OFF);
    float*    sxn = (float*)(sm + KS_OFF);

    const int qg  = blockIdx.x;     // 0..15 (64 queries each)
    const int b   = blockIdx.y;     // 0..15
    const int tid = threadIdx.x;    // 256
    const int warp = tid >> 5, lane = tid & 31;
    const int wy = warp & 1, wx = warp >> 1;
    const int r = lane >> 2, c = lane & 3;

    // load Q: 64 gathered rows x 256 bf16
    #pragma unroll
    for (int it = 0; it < 8; it++) {
        int idx = tid + it*256;           // 0..2047
        int row = idx >> 5, u = idx & 31;
        int g = g_fps[b*NS + qg*64 + row];
        uint4 v = ((const uint4*)g_fhi)[(size_t)g*32 + u];
        *(uint4*)((char*)QsU + row*528 + u*16) = v;
    }

    float tv[16]; int tx[16];
    #pragma unroll
    for (int j = 0; j < 16; j++) { tv[j] = finf(); tx[j] = 0; }
    float wcur = finf(); int wpos = 0;

    for (int c0 = 0; c0 < NP; c0 += 128) {
        float acc[2][4][4] = {};
        for (int kt = 0; kt < 4; kt++) {
            __syncthreads();
            // X sub-chunk: 128 cands x 64 k bf16
            #pragma unroll
            for (int it = 0; it < 4; it++) {
                int idx = tid + it*256;       // 0..1023
                int row = idx >> 3, u = idx & 7;
                uint4 v = ((const uint4*)g_fhi)[(size_t)(b*NP + c0 + row)*32 + kt*8 + u];
                *(uint4*)((char*)XsU + row*144 + u*16) = v;
            }
            if (kt == 0 && tid < 128) sxn[tid] = g_xnorm[b*NP + c0 + tid];
            __syncthreads();
            #pragma unroll
            for (int ks = 0; ks < 4; ks++) {
                const int koq = kt*32 + ks*8 + c;   // word offset into Qs row
                const int kox = ks*8 + c;           // word offset into Xs row
                unsigned bb[4][2];
                #pragma unroll
                for (int nf = 0; nf < 4; nf++) {
                    int n = wx*32 + nf*8 + r;
                    bb[nf][0] = XsU[n*36 + kox];
                    bb[nf][1] = XsU[n*36 + kox + 4];
                }
                #pragma unroll
                for (int mf = 0; mf < 2; mf++) {
                    int mb = wy*32 + mf*16;
                    unsigned a0 = QsU[(mb+r  )*132 + koq];
                    unsigned a1 = QsU[(mb+r+8)*132 + koq];
                    unsigned a2 = QsU[(mb+r  )*132 + koq + 4];
                    unsigned a3 = QsU[(mb+r+8)*132 + koq + 4];
                    #pragma unroll
                    for (int nf = 0; nf < 4; nf++)
                        mma16(acc[mf][nf], a0,a1,a2,a3, bb[nf][0], bb[nf][1]);
                }
            }
        }
        // distances -> Ds
        #pragma unroll
        for (int mf = 0; mf < 2; mf++) {
            int q0 = wy*32 + mf*16 + r;
            #pragma unroll
            for (int nf = 0; nf < 4; nf++) {
                int col = wx*32 + nf*8 + 2*c;
                float x0 = sxn[col], x1 = sxn[col+1];
                Ds[q0*133 + col]     = fmaf(-2.f, acc[mf][nf][0], x0);
                Ds[q0*133 + col + 1] = fmaf(-2.f, acc[mf][nf][1], x1);
                Ds[(q0+8)*133 + col]     = fmaf(-2.f, acc[mf][nf][2], x0);
                Ds[(q0+8)*133 + col + 1] = fmaf(-2.f, acc[mf][nf][3], x1);
            }
        }
        __syncthreads();
        // selection: 128 threads = 64 q x 2 slices of 64 cols, register top-16
        if (tid < 128) {
            const int q = tid & 63, sl = tid >> 6;
            const float* dsrow = Ds + q*133 + sl*64;
            #pragma unroll 1
            for (int cc = 0; cc < 64; cc++) {
                float d = dsrow[cc];
                if (d < wcur) {
                    int idx = c0 + sl*64 + cc;
                    #pragma unroll
                    for (int j = 0; j < 16; j++)
                        if (j == wpos) { tv[j] = d; tx[j] = idx; }
                    wcur = tv[0]; wpos = 0;
                    #pragma unroll
                    for (int j = 1; j < 16; j++)
                        if (tv[j] > wcur) { wcur = tv[j]; wpos = j; }
                }
            }
        }
    }
    if (tid < 128) {
        const int q = tid & 63, sl = tid >> 6;
        const int qglob = b*NS + qg*64 + q;
        #pragma unroll
        for (int j = 0; j < 16; j++)
            g_knn32[(size_t)qglob*NK2 + sl*16 + j] = b*NP + tx[j];
    }
}

// ======================= exact fp32 rescore: 32 -> top-16 ====================
__global__ void k_rescore(const float* __restrict__ feat) {
    __shared__ float sdist[NK2];
    __shared__ int   sgid[NK2];
    const int q   = blockIdx.x;
    const int tid = threadIdx.x;      // 256
    const int cidx = tid >> 3;
    const int seg  = tid & 7;
    const int gq = g_fps[q];
    const int gc = g_knn32[q*NK2 + cidx];
    const float4* qp = (const float4*)(feat + (size_t)gq * FIN);
    const float4* xp = (const float4*)(feat + (size_t)gc * FIN);
    float s = 0.f;
    #pragma unroll
    for (int i = 0; i < 8; i++) {
        float4 qv = qp[seg*8 + i];
        float4 xv = xp[seg*8 + i];
        s += qv.x*xv.x + qv.y*xv.y + qv.z*xv.z + qv.w*xv.w;
    }
    s += __shfl_down_sync(0xffffffffu, s, 4);
    s += __shfl_down_sync(0xffffffffu, s, 2);
    s += __shfl_down_sync(0xffffffffu, s, 1);
    if (seg == 0) { sdist[cidx] = fmaf(-2.f, s, g_xnorm[gc]); sgid[cidx] = gc; }
    __syncthreads();
    if (tid == 0) {
        #pragma unroll 1
        for (int j = 0; j < NK; j++) {
            float best = finf(); int bi = 0x7fffffff, bp = 0;
            for (int c2 = 0; c2 < NK2; c2++) {
                float d = sdist[c2]; int g = sgid[c2];
                if (d < best || (d == best && g < bi)) { best = d; bi = g; bp = c2; }
            }
            g_knn[q*NK + j] = bi;
            sdist[bp] = finf();
        }
    }
}

// ======================= gather + norm + relu + max-pool =====================
__global__ void k_pool(const float* __restrict__ gamma, const float* __restrict__ beta,
                       float* __restrict__ out) {
    const int rrow = blockIdx.x;
    const int t = threadIdx.x;     // 128
    __shared__ int nb[NK];
    if (t < NK) nb[t] = g_knn[rrow*NK + t];
    __syncthreads();
    float a[4], c[4], m[4];
    #pragma unroll
    for (int i = 0; i < 4; i++) {
        int col = t + i*128;
        float aa = gamma[col] * g_rsig[col];
        a[i] = aa;
        c[i] = beta[col] - aa * g_mu[col];
        m[i] = -finf();
    }
    for (int j = 0; j < NK; j++) {
        const float* hr = g_h + (size_t)nb[j] * FOUT;
        #pragma unroll
        for (int i = 0; i < 4; i++)
            m[i] = fmaxf(m[i], fmaf(a[i], hr[t + i*128], c[i]));
    }
    #pragma unroll
    for (int i = 0; i < 4; i++)
        out[(size_t)rrow*FOUT + t + i*128] = fmaxf(m[i], 0.0f);
}

// ======================= fps positions + batch ===============================
__global__ void k_meta(const float* __restrict__ pos,
                       float* __restrict__ out_pos, float* __restrict__ out_batch) {
    const int rrow = blockIdx.x * 1024 + threadIdx.x;
    int g = g_fps[rrow];
    if (out_pos) {
        out_pos[rrow*3 + 0] = pos[(size_t)g*3 + 0];
        out_pos[rrow*3 + 1] = pos[(size_t)g*3 + 1];
        out_pos[rrow*3 + 2] = pos[(size_t)g*3 + 2];
    }
    if (out_batch) out_batch[rrow] = (float)(g >> 12);
}

// ======================= launch =======================
extern "C" void kernel_launch(void* const* d_in, const int* in_sizes, int n_in,
                              void* d_out, int out_size) {
    const float* features  = (const float*)d_in[0];
    const float* positions = (const float*)d_in[1];
    const float* W     = (const float*)d_in[3];
    const float* bias  = (const float*)d_in[4];
    const float* gamma = (const float*)d_in[5];
    const float* beta  = (const float*)d_in[6];
    float* out = (float*)d_out;

    cudaFuncSetAttribute(k_fused, cudaFuncAttributeMaxDynamicSharedMemorySize, FUSED_SMEM);
    cudaFuncSetAttribute(k_knn,   cudaFuncAttributeMaxDynamicSharedMemorySize, KNN_SMEM);

    const long NFE = (long)NQ * FOUT;
    float* out_pos   = (out_size >= NFE + NQ*3)      ? out + NFE        : nullptr;
    float* out_batch = (out_size >= NFE + NQ*3 + NQ) ? out + NFE + NQ*3 : nullptr;

    k_fused   <<<16 + 4096 + 256, 256, FUSED_SMEM>>>(features, positions, W, bias);
    k_stats   <<<256, 256>>>();
    k_finalize<<<8, 512>>>();
    k_knn     <<<dim3(16, 16), 256, KNN_SMEM>>>();
    k_rescore <<<NQ, 256>>>(features);
    k_pool    <<<NQ, 128>>>(gamma, beta, out);
    k_meta    <<<NB, 1024>>>(positions, out_pos, out_batch);
}